// round 4
// baseline (speedup 1.0000x reference)
#include <cuda_runtime.h>
#include <math.h>

#define G 8192
#define S 64
#define D 128
#define H 256
#define EPS 0.01f
#define GPB 8          // groups per block

// Output layout: rep [G*D] | mixture [G*8] | scale [G] | alpha [G] | beta [G]
#define O_REP   0
#define O_MIX   (G * D)
#define O_SCALE (O_MIX + G * 8)
#define O_ALPHA (O_SCALE + G)
#define O_BETA  (O_ALPHA + G)

__device__ __forceinline__ float softplus_f(float v) {
    return fmaxf(v, 0.f) + log1pf(expf(-fabsf(v)));
}

// ---------------------------------------------------------------------------
// Fully fused kernel. Block = 256 threads = 8 warps = 8 groups.
// Phase 1: warp-per-group streaming stats -> rep (gmem + smem).
// Phase 2: block GEMM1 (8x128 @ 128x256), W1 streamed from L2, tanh -> smem.
// Phase 3: warp-per-group GEMM2 (256x10) + softplus/softmax epilogue.
// ---------------------------------------------------------------------------
__global__ __launch_bounds__(256) void fused_kernel(
    const float* __restrict__ x, const float* __restrict__ y,
    const float* __restrict__ ax, const float* __restrict__ ay,
    const float* __restrict__ W1, const float* __restrict__ b1,
    const float* __restrict__ W2, const float* __restrict__ b2,
    float* __restrict__ out)
{
    __shared__ float sA[GPB * D];      // 4 KB  rep per group
    __shared__ float sH[GPB * H];      // 8 KB  hidden activations
    __shared__ float sW2[H * 10];      // 10 KB

    const int t = threadIdx.x;
    const int warp = t >> 5;
    const int lane = t & 31;
    const int g = blockIdx.x * GPB + warp;

    // W2 cooperative load (overlaps with stream below)
    for (int i = t; i < H * 10; i += 256) sW2[i] = W2[i];

    // ---------------- Phase 1: per-group stats ----------------
    {
        const float4* xg = reinterpret_cast<const float4*>(x + (size_t)g * S * D) + lane;
        const float4  a4 = reinterpret_cast<const float4*>(ax + (size_t)g * D)[lane];
        const float   ayv = ay[g];
        const float*  yg = y + (size_t)g * S;

        float sx0 = 0.f, sx1 = 0.f, sx2 = 0.f, sx3 = 0.f;
        float sp0 = 0.f, sp1 = 0.f, sp2 = 0.f, sp3 = 0.f;
        float sxx = 0.f, sy = 0.f;

        for (int s0 = 0; s0 < S; s0 += 8) {
            float4 xv[8];
            float  yv[8];
#pragma unroll
            for (int i = 0; i < 8; ++i) xv[i] = xg[(s0 + i) * 32];
#pragma unroll
            for (int i = 0; i < 8; ++i) yv[i] = __ldg(yg + s0 + i);
#pragma unroll
            for (int i = 0; i < 8; ++i) {
                float xr0 = xv[i].x - a4.x;
                float xr1 = xv[i].y - a4.y;
                float xr2 = xv[i].z - a4.z;
                float xr3 = xv[i].w - a4.w;
                float yr  = yv[i] - ayv;
                sx0 += xr0; sx1 += xr1; sx2 += xr2; sx3 += xr3;
                sp0 += xr0 * yr; sp1 += xr1 * yr; sp2 += xr2 * yr; sp3 += xr3 * yr;
                sxx += xr0 * xr0 + xr1 * xr1 + xr2 * xr2 + xr3 * xr3;
                sy  += yr;
            }
        }

        float tot = sx0 + sx1 + sx2 + sx3;
        float sxxT = sxx;
#pragma unroll
        for (int o = 16; o > 0; o >>= 1) {
            tot  += __shfl_xor_sync(0xffffffffu, tot,  o);
            sxxT += __shfl_xor_sync(0xffffffffu, sxxT, o);
        }

        const float nD = (float)(S * D);
        const float var = (sxxT - tot * tot / nD) / (nD - 1.f);
        const float inv = 1.f / var;
        const float invn  = 1.f / (float)S;
        const float invn1 = 1.f / (float)(S - 1);

        float4 r;
        r.x = (sp0 - sx0 * sy * invn) * invn1 * inv;
        r.y = (sp1 - sx1 * sy * invn) * invn1 * inv;
        r.z = (sp2 - sx2 * sy * invn) * invn1 * inv;
        r.w = (sp3 - sx3 * sy * invn) * invn1 * inv;
        reinterpret_cast<float4*>(out + O_REP + (size_t)g * D)[lane] = r;
        reinterpret_cast<float4*>(sA + warp * D)[lane] = r;
    }
    __syncthreads();

    // ---------------- Phase 2: GEMM1 + tanh ----------------
    // Thread computes rows {rr, rr+1} x cols [c0, c0+4). rr=(t>>6)*2, c0=(t&63)*4.
    {
        const int rr = (t >> 6) * 2;
        const int c0 = (t & 63) * 4;
        const float* A0 = sA + rr * D;
        const float* A1 = A0 + D;
        const float4* W1v = reinterpret_cast<const float4*>(W1) + (c0 >> 2);

        float4 acc0 = {0.f, 0.f, 0.f, 0.f};
        float4 acc1 = {0.f, 0.f, 0.f, 0.f};
#pragma unroll 8
        for (int k = 0; k < D; ++k) {
            float4 w = W1v[k * (H / 4)];
            float a0 = A0[k];
            float a1 = A1[k];
            acc0.x += a0 * w.x; acc0.y += a0 * w.y;
            acc0.z += a0 * w.z; acc0.w += a0 * w.w;
            acc1.x += a1 * w.x; acc1.y += a1 * w.y;
            acc1.z += a1 * w.z; acc1.w += a1 * w.w;
        }
        float4 bb = reinterpret_cast<const float4*>(b1)[c0 >> 2];
        float4 h0, h1;
        h0.x = tanhf(acc0.x + bb.x); h0.y = tanhf(acc0.y + bb.y);
        h0.z = tanhf(acc0.z + bb.z); h0.w = tanhf(acc0.w + bb.w);
        h1.x = tanhf(acc1.x + bb.x); h1.y = tanhf(acc1.y + bb.y);
        h1.z = tanhf(acc1.z + bb.z); h1.w = tanhf(acc1.w + bb.w);
        reinterpret_cast<float4*>(sH + rr * H + c0)[0] = h0;
        reinterpret_cast<float4*>(sH + (rr + 1) * H + c0)[0] = h1;
    }
    __syncthreads();

    // ---------------- Phase 3: GEMM2 + epilogue (warp = group) ----------------
    {
        float p[10];
#pragma unroll
        for (int k = 0; k < 10; ++k) p[k] = 0.f;

        const float* hrow = sH + warp * H;
#pragma unroll
        for (int j = 0; j < 8; ++j) {
            float hv = hrow[lane + 32 * j];
            const float* w2r = sW2 + (lane + 32 * j) * 10;
#pragma unroll
            for (int k = 0; k < 10; ++k) p[k] += hv * w2r[k];
        }
#pragma unroll
        for (int k = 0; k < 10; ++k) {
#pragma unroll
            for (int o = 16; o > 0; o >>= 1)
                p[k] += __shfl_xor_sync(0xffffffffu, p[k], o);
        }

        if (lane == 0) {
            float o0 = p[0] + b2[0];
            float o1 = p[1] + b2[1];
            float alpha = softplus_f(o0) * (1.f - EPS) + EPS;
            float beta  = softplus_f(o1) * (1.f - EPS) + EPS;

            float lg[8];
            float mx = -3.4e38f;
#pragma unroll
            for (int k = 0; k < 8; ++k) {
                lg[k] = p[2 + k] + b2[2 + k];
                mx = fmaxf(mx, lg[k]);
            }
            float se = 0.f;
#pragma unroll
            for (int k = 0; k < 8; ++k) { lg[k] = expf(lg[k] - mx); se += lg[k]; }
            float inv_se = 1.f / se;
#pragma unroll
            for (int k = 0; k < 8; ++k) out[O_MIX + (size_t)g * 8 + k] = lg[k] * inv_se;

            out[O_SCALE + g] = sqrtf(beta / alpha);
            out[O_ALPHA + g] = alpha;
            out[O_BETA  + g] = beta;
        }
    }
}

// ---------------------------------------------------------------------------
extern "C" void kernel_launch(void* const* d_in, const int* in_sizes, int n_in,
                              void* d_out, int out_size)
{
    (void)in_sizes; (void)n_in; (void)out_size;
    // inputs: 0=index(int32), 1=x, 2=y, 3=anchor_x, 4=anchor_y, 5=W1, 6=b1, 7=W2, 8=b2
    const float* x  = (const float*)d_in[1];
    const float* y  = (const float*)d_in[2];
    const float* ax = (const float*)d_in[3];
    const float* ay = (const float*)d_in[4];
    const float* W1 = (const float*)d_in[5];
    const float* b1 = (const float*)d_in[6];
    const float* W2 = (const float*)d_in[7];
    const float* b2 = (const float*)d_in[8];
    float* out = (float*)d_out;

    fused_kernel<<<G / GPB, 256>>>(x, y, ax, ay, W1, b1, W2, b2, out);
}

// round 5
// speedup vs baseline: 1.1620x; 1.1620x over previous
#include <cuda_runtime.h>
#include <math.h>

#define G 8192
#define S 64
#define D 128
#define H 256
#define EPS 0.01f

// Output layout: rep [G*D] | mixture [G*8] | scale [G] | alpha [G] | beta [G]
#define O_REP   0
#define O_MIX   (G * D)
#define O_SCALE (O_MIX + G * 8)
#define O_ALPHA (O_SCALE + G)
#define O_BETA  (O_ALPHA + G)

// ---------------------------------------------------------------------------
// Kernel 1: per-group statistics -> rep (unchanged, proven ~49us / 5.4 TB/s)
// ---------------------------------------------------------------------------
__global__ __launch_bounds__(256) void stats_kernel(
    const float* __restrict__ x, const float* __restrict__ y,
    const float* __restrict__ ax, const float* __restrict__ ay,
    float* __restrict__ rep)
{
    const int warp = threadIdx.x >> 5;
    const int lane = threadIdx.x & 31;
    const int g = blockIdx.x * 8 + warp;

    const float4* xg = reinterpret_cast<const float4*>(x + (size_t)g * S * D) + lane;
    const float4  a4 = reinterpret_cast<const float4*>(ax + (size_t)g * D)[lane];
    const float   ayv = ay[g];
    const float*  yg = y + (size_t)g * S;

    float sx0 = 0.f, sx1 = 0.f, sx2 = 0.f, sx3 = 0.f;
    float sp0 = 0.f, sp1 = 0.f, sp2 = 0.f, sp3 = 0.f;
    float sxx = 0.f, sy = 0.f;

#pragma unroll 4
    for (int s = 0; s < S; ++s) {
        float4 xv = xg[s * 32];
        float  yv = __ldg(yg + s);
        float xr0 = xv.x - a4.x;
        float xr1 = xv.y - a4.y;
        float xr2 = xv.z - a4.z;
        float xr3 = xv.w - a4.w;
        float yr  = yv - ayv;
        sx0 += xr0; sx1 += xr1; sx2 += xr2; sx3 += xr3;
        sp0 += xr0 * yr; sp1 += xr1 * yr; sp2 += xr2 * yr; sp3 += xr3 * yr;
        sxx += xr0 * xr0 + xr1 * xr1 + xr2 * xr2 + xr3 * xr3;
        sy  += yr;
    }

    float tot = sx0 + sx1 + sx2 + sx3;
    float sxxT = sxx;
#pragma unroll
    for (int o = 16; o > 0; o >>= 1) {
        tot  += __shfl_xor_sync(0xffffffffu, tot,  o);
        sxxT += __shfl_xor_sync(0xffffffffu, sxxT, o);
    }

    const float nD = (float)(S * D);
    const float var = (sxxT - tot * tot / nD) / (nD - 1.f);
    const float inv = 1.f / var;
    const float invn  = 1.f / (float)S;
    const float invn1 = 1.f / (float)(S - 1);

    float4 r;
    r.x = (sp0 - sx0 * sy * invn) * invn1 * inv;
    r.y = (sp1 - sx1 * sy * invn) * invn1 * inv;
    r.z = (sp2 - sx2 * sy * invn) * invn1 * inv;
    r.w = (sp3 - sx3 * sy * invn) * invn1 * inv;
    reinterpret_cast<float4*>(rep + (size_t)g * D)[lane] = r;
}

// ---------------------------------------------------------------------------
// Kernel 2: MLP head, redesigned for occupancy.
// Grid = 256 blocks x 256 threads. Block owns 32 groups x full H=256.
// W1 consumed in 4 k-chunks of 32x256 via a 32KB smem buffer (not resident).
// Thread micro-tile: 8 rows x 4 cols. Then GEMM2 + epilogue fused (warp
// handles 4 groups).
// ---------------------------------------------------------------------------
__device__ __forceinline__ float softplus_f(float v) {
    return fmaxf(v, 0.f) + log1pf(expf(-fabsf(v)));
}

#define ROWS 32                 // groups per block
#define KC   32                 // k-chunk depth

__global__ __launch_bounds__(256, 2) void mlp_kernel(
    const float* __restrict__ rep, const float* __restrict__ W1,
    const float* __restrict__ b1, const float* __restrict__ W2,
    const float* __restrict__ b2, float* __restrict__ out)
{
    __shared__ float sA[ROWS * D];      // 16 KB
    __shared__ float sW[KC * H];        // 32 KB
    __shared__ float sH[ROWS * H];      // 32 KB
    __shared__ float sW2[H * 10];       // 10 KB

    const int t = threadIdx.x;
    const int rgrp = t >> 6;            // 0..3 -> rows [8*rgrp, 8*rgrp+8)
    const int c0 = (t & 63) * 4;        // cols [c0, c0+4)

    // load A tile (32 rows of rep) and W2
    {
        const float4* src = reinterpret_cast<const float4*>(rep + (size_t)blockIdx.x * ROWS * D);
        float4* dst = reinterpret_cast<float4*>(sA);
#pragma unroll
        for (int i = 0; i < 4; ++i) dst[t + i * 256] = src[t + i * 256];
    }
    for (int i = t; i < H * 10; i += 256) sW2[i] = W2[i];

    float acc[8][4];
#pragma unroll
    for (int r = 0; r < 8; ++r)
#pragma unroll
        for (int j = 0; j < 4; ++j) acc[r][j] = 0.f;

    const float* Abase = sA + rgrp * 8 * D;

    for (int c = 0; c < D / KC; ++c) {
        // cooperative load of W1 chunk [32 x 256] = 2048 float4
        {
            const float4* src = reinterpret_cast<const float4*>(W1 + c * KC * H);
            float4* dst = reinterpret_cast<float4*>(sW);
#pragma unroll
            for (int i = 0; i < 8; ++i) dst[t + i * 256] = src[t + i * 256];
        }
        __syncthreads();

#pragma unroll
        for (int kk = 0; kk < KC; ++kk) {
            const int k = c * KC + kk;
            float4 w = *reinterpret_cast<const float4*>(sW + kk * H + c0);
            float a[8];
#pragma unroll
            for (int r = 0; r < 8; ++r) a[r] = Abase[r * D + k];  // broadcast
#pragma unroll
            for (int r = 0; r < 8; ++r) {
                acc[r][0] += a[r] * w.x;
                acc[r][1] += a[r] * w.y;
                acc[r][2] += a[r] * w.z;
                acc[r][3] += a[r] * w.w;
            }
        }
        __syncthreads();
    }

    // bias + tanh -> sH
    {
        float4 bb = reinterpret_cast<const float4*>(b1)[c0 >> 2];
#pragma unroll
        for (int r = 0; r < 8; ++r) {
            float4 h;
            h.x = tanhf(acc[r][0] + bb.x);
            h.y = tanhf(acc[r][1] + bb.y);
            h.z = tanhf(acc[r][2] + bb.z);
            h.w = tanhf(acc[r][3] + bb.w);
            *reinterpret_cast<float4*>(sH + (rgrp * 8 + r) * H + c0) = h;
        }
    }
    __syncthreads();

    // GEMM2 + epilogue: warp w handles groups [4w, 4w+4)
    const int warp = t >> 5;
    const int lane = t & 31;

#pragma unroll
    for (int i = 0; i < 4; ++i) {
        const int row = warp * 4 + i;
        const float* hrow = sH + row * H;

        float p[10];
#pragma unroll
        for (int k = 0; k < 10; ++k) p[k] = 0.f;

#pragma unroll
        for (int j = 0; j < 8; ++j) {
            float hv = hrow[lane + 32 * j];
            const float* w2r = sW2 + (lane + 32 * j) * 10;
#pragma unroll
            for (int k = 0; k < 10; ++k) p[k] += hv * w2r[k];
        }
#pragma unroll
        for (int k = 0; k < 10; ++k) {
#pragma unroll
            for (int o = 16; o > 0; o >>= 1)
                p[k] += __shfl_xor_sync(0xffffffffu, p[k], o);
        }

        if (lane == 0) {
            const int g = blockIdx.x * ROWS + row;
            float o0 = p[0] + b2[0];
            float o1 = p[1] + b2[1];
            float alpha = softplus_f(o0) * (1.f - EPS) + EPS;
            float beta  = softplus_f(o1) * (1.f - EPS) + EPS;

            float lg[8];
            float mx = -3.4e38f;
#pragma unroll
            for (int k = 0; k < 8; ++k) {
                lg[k] = p[2 + k] + b2[2 + k];
                mx = fmaxf(mx, lg[k]);
            }
            float se = 0.f;
#pragma unroll
            for (int k = 0; k < 8; ++k) { lg[k] = expf(lg[k] - mx); se += lg[k]; }
            float inv_se = 1.f / se;
#pragma unroll
            for (int k = 0; k < 8; ++k) out[O_MIX + (size_t)g * 8 + k] = lg[k] * inv_se;

            out[O_SCALE + g] = sqrtf(beta / alpha);
            out[O_ALPHA + g] = alpha;
            out[O_BETA  + g] = beta;
        }
    }
}

// ---------------------------------------------------------------------------
extern "C" void kernel_launch(void* const* d_in, const int* in_sizes, int n_in,
                              void* d_out, int out_size)
{
    (void)in_sizes; (void)n_in; (void)out_size;
    // inputs: 0=index(int32), 1=x, 2=y, 3=anchor_x, 4=anchor_y, 5=W1, 6=b1, 7=W2, 8=b2
    const float* x  = (const float*)d_in[1];
    const float* y  = (const float*)d_in[2];
    const float* ax = (const float*)d_in[3];
    const float* ay = (const float*)d_in[4];
    const float* W1 = (const float*)d_in[5];
    const float* b1 = (const float*)d_in[6];
    const float* W2 = (const float*)d_in[7];
    const float* b2 = (const float*)d_in[8];
    float* out = (float*)d_out;

    stats_kernel<<<G / 8, 256>>>(x, y, ax, ay, out + O_REP);
    mlp_kernel<<<G / ROWS, 256>>>(out + O_REP, W1, b1, W2, b2, out);
}